// round 6
// baseline (speedup 1.0000x reference)
#include <cuda_runtime.h>
#include <math.h>

typedef unsigned long long u64;

// ---- packed f32x2 helpers ----
__device__ __forceinline__ u64 pk2(float lo, float hi) {
    u64 r; asm("mov.b64 %0,{%1,%2};" : "=l"(r) : "f"(lo), "f"(hi)); return r;
}
__device__ __forceinline__ void upk2(float& lo, float& hi, u64 v) {
    asm("mov.b64 {%0,%1},%2;" : "=f"(lo), "=f"(hi) : "l"(v));
}
__device__ __forceinline__ u64 fma2(u64 a, u64 b, u64 c) {
    u64 d; asm("fma.rn.f32x2 %0,%1,%2,%3;" : "=l"(d) : "l"(a), "l"(b), "l"(c)); return d;
}
__device__ __forceinline__ u64 mul2(u64 a, u64 b) {
    u64 d; asm("mul.rn.f32x2 %0,%1,%2;" : "=l"(d) : "l"(a), "l"(b)); return d;
}

// ---------------------------------------------------------------------------
// Gate templates (compile-time masks). Wire w <-> bit (3-w) of amp index.
// ---------------------------------------------------------------------------
template<int M>
__device__ __forceinline__ void ry_gate(float sr[16], float si[16], float c, float s) {
#pragma unroll
    for (int i = 0; i < 16; i++) {
        if (!(i & M)) {
            const int j = i | M;
            float a0r = sr[i], a0i = si[i], a1r = sr[j], a1i = si[j];
            sr[i] = c * a0r - s * a1r;
            si[i] = c * a0i - s * a1i;
            sr[j] = s * a0r + c * a1r;
            si[j] = s * a0i + c * a1i;
        }
    }
}

template<int M>
__device__ __forceinline__ void rz_gate(float sr[16], float si[16], float c, float s) {
#pragma unroll
    for (int i = 0; i < 16; i++) {
        float sg = (i & M) ? s : -s;
        float rr = sr[i], ii = si[i];
        sr[i] = c * rr - sg * ii;
        si[i] = c * ii + sg * rr;
    }
}

template<int CM, int TM>
__device__ __forceinline__ void cx_gate(float sr[16], float si[16]) {
#pragma unroll
    for (int i = 0; i < 16; i++) {
        if ((i & CM) && !(i & TM)) {
            const int j = i | TM;
            float t;
            t = sr[i]; sr[i] = sr[j]; sr[j] = t;
            t = si[i]; si[i] = si[j]; si[j] = t;
        }
    }
}

// Coefficient tensor, layout [i(a12)][w][12]: j pairs at 0..8, pad 9..11.
__device__ float g_A[9 * 4 * 12];

// ---------------------------------------------------------------------------
// Precompute kernel (1 block): U, O_w = U^dag Z_w U, multilinear coeffs.
// ---------------------------------------------------------------------------
__global__ void precompute_A_kernel(const float* __restrict__ vp) {
    __shared__ float vc[24], vs[24];
    __shared__ float Ur[16][16], Ui[16][16];
    __shared__ float ReO[4][16][16];

    const int tid = threadIdx.x;

    for (int i = tid; i < 9 * 4 * 12; i += 324) g_A[i] = 0.0f;

    if (tid < 24) {
        float ss, cc;
        __sincosf(vp[tid] * 0.5f, &ss, &cc);
        vc[tid] = cc;
        vs[tid] = ss;
    }
    __syncthreads();

    if (tid < 16) {
        float sr[16], si[16];
#pragma unroll
        for (int i = 0; i < 16; i++) { sr[i] = 0.0f; si[i] = 0.0f; }
        sr[tid] = 1.0f;

#pragma unroll
        for (int l = 0; l < 3; l++) {
            const float* lc = vc + l * 8;
            const float* ls = vs + l * 8;
            ry_gate<8>(sr, si, lc[0], ls[0]); rz_gate<8>(sr, si, lc[1], ls[1]);
            ry_gate<4>(sr, si, lc[1], ls[1]); rz_gate<4>(sr, si, lc[2], ls[2]);
            ry_gate<2>(sr, si, lc[2], ls[2]); rz_gate<2>(sr, si, lc[3], ls[3]);
            ry_gate<1>(sr, si, lc[3], ls[3]); rz_gate<1>(sr, si, lc[4], ls[4]);
            cx_gate<8, 4>(sr, si);
            cx_gate<4, 2>(sr, si);
            cx_gate<2, 1>(sr, si);
            cx_gate<1, 8>(sr, si);
        }
#pragma unroll
        for (int k = 0; k < 16; k++) { Ur[k][tid] = sr[k]; Ui[k][tid] = si[k]; }
    }
    __syncthreads();

    if (tid < 256) {
        const int i = tid >> 4;
        const int j = tid & 15;
        float acc[4] = {0.0f, 0.0f, 0.0f, 0.0f};
#pragma unroll
        for (int k = 0; k < 16; k++) {
            float t = Ur[k][i] * Ur[k][j] + Ui[k][i] * Ui[k][j];
#pragma unroll
            for (int w = 0; w < 4; w++)
                acc[w] += (k & (8 >> w)) ? -t : t;
        }
#pragma unroll
        for (int w = 0; w < 4; w++) ReO[w][i][j] = acc[w];
    }
    __syncthreads();

    if (tid < 324) {
        const int w = tid / 81;
        const int a = tid % 81;
        const int a0 = a / 27, a1 = (a / 9) % 3, a2 = (a / 3) % 3, a3 = a % 3;
        const int zm = (a0 == 1 ? 8 : 0) | (a1 == 1 ? 4 : 0) | (a2 == 1 ? 2 : 0) | (a3 == 1 ? 1 : 0);
        const int xm = (a0 == 2 ? 8 : 0) | (a1 == 2 ? 4 : 0) | (a2 == 2 ? 2 : 0) | (a3 == 2 ? 1 : 0);
        float acc = 0.0f;
#pragma unroll
        for (int i = 0; i < 16; i++) {
            float v = ReO[w][i][i ^ xm];
            acc += (__popc(i & zm) & 1) ? -v : v;
        }
        const int a12 = a0 * 3 + a1;
        const int a34 = a2 * 3 + a3;
        g_A[(a12 * 4 + w) * 12 + a34] = acc * 0.0625f;
    }
}

// ---------------------------------------------------------------------------
// Main fused kernel: one block per IMAGE PAIR. Packed-pair contraction
// (LDS.128 ulonglong2 + FFMA2), feats->smem, packed warp-GEMM, log_softmax.
// ---------------------------------------------------------------------------
__global__ __launch_bounds__(224, 4) void quanv_fused6_kernel(
    const float* __restrict__ x,     // (B,1,28,28)
    const float* __restrict__ W,     // (10,784)
    const float* __restrict__ bias,  // (10,)
    float* __restrict__ out,         // (B,10)
    int B)
{
    const int b0   = 2 * blockIdx.x;
    const int b1   = b0 + 1;
    const bool has1 = (b1 < B);
    const int tid  = threadIdx.x;
    const int warp = tid >> 5;
    const int lane = tid & 31;

    __shared__ __align__(16) float sA[9 * 4 * 12];
    __shared__ __align__(16) float4 feats[2][196];
    __shared__ float slog[20];
    __shared__ float slse[2];

    for (int i = tid; i < 9 * 4 * 12; i += 224)
        sA[i] = g_A[i];
    __syncthreads();

    if (tid < 196) {
        const int r14 = tid / 14;
        const int c14 = tid % 14;
        const int off = (2 * r14) * 28 + 2 * c14;

        // ---- image 0 angles ----
        float g12a[9];
        u64 Ga[5];
        {
            const float* xa = x + (size_t)b0 * 784;
            const float2 t2 = *reinterpret_cast<const float2*>(xa + off);
            const float2 b2 = *reinterpret_cast<const float2*>(xa + off + 28);
            float c0, s0, c1, s1, c2, s2, c3, s3;
            __sincosf(t2.x, &s0, &c0);
            __sincosf(t2.y, &s1, &c1);
            __sincosf(b2.x, &s2, &c2);
            __sincosf(b2.y, &s3, &c3);
            g12a[0] = 1.0f; g12a[1] = c1;      g12a[2] = s1;
            g12a[3] = c0;   g12a[4] = c0 * c1; g12a[5] = c0 * s1;
            g12a[6] = s0;   g12a[7] = s0 * c1; g12a[8] = s0 * s1;
            Ga[0] = pk2(1.0f,    c3);
            Ga[1] = pk2(s3,      c2);
            Ga[2] = pk2(c2 * c3, c2 * s3);
            Ga[3] = pk2(s2,      s2 * c3);
            Ga[4] = pk2(s2 * s3, 0.0f);
        }

        // ---- image 1 angles ----
        float g12b[9];
        u64 Gb[5];
        if (has1) {
            const float* xb = x + (size_t)b1 * 784;
            const float2 t2 = *reinterpret_cast<const float2*>(xb + off);
            const float2 b2 = *reinterpret_cast<const float2*>(xb + off + 28);
            float c0, s0, c1, s1, c2, s2, c3, s3;
            __sincosf(t2.x, &s0, &c0);
            __sincosf(t2.y, &s1, &c1);
            __sincosf(b2.x, &s2, &c2);
            __sincosf(b2.y, &s3, &c3);
            g12b[0] = 1.0f; g12b[1] = c1;      g12b[2] = s1;
            g12b[3] = c0;   g12b[4] = c0 * c1; g12b[5] = c0 * s1;
            g12b[6] = s0;   g12b[7] = s0 * c1; g12b[8] = s0 * s1;
            Gb[0] = pk2(1.0f,    c3);
            Gb[1] = pk2(s3,      c2);
            Gb[2] = pk2(c2 * c3, c2 * s3);
            Gb[3] = pk2(s2,      s2 * c3);
            Gb[4] = pk2(s2 * s3, 0.0f);
        } else {
#pragma unroll
            for (int i = 0; i < 9; i++) g12b[i] = 0.0f;
#pragma unroll
            for (int i = 0; i < 5; i++) Gb[i] = 0ull;
        }

        // ---- packed contraction ----
        u64 e2a[4] = {0ull, 0ull, 0ull, 0ull};
        u64 e2b[4] = {0ull, 0ull, 0ull, 0ull};
#pragma unroll
        for (int i = 0; i < 9; i++) {
            const u64 gda = pk2(g12a[i], g12a[i]);
            const u64 gdb = pk2(g12b[i], g12b[i]);
#pragma unroll
            for (int w = 0; w < 4; w++) {
                const float* rowf = &sA[(i * 4 + w) * 12];
                const ulonglong2 q01 = *reinterpret_cast<const ulonglong2*>(rowf);
                const ulonglong2 q23 = *reinterpret_cast<const ulonglong2*>(rowf + 4);
                const u64        q4  = *reinterpret_cast<const u64*>(rowf + 8);

                u64 ta = mul2(q01.x, Ga[0]);
                ta = fma2(q01.y, Ga[1], ta);
                ta = fma2(q23.x, Ga[2], ta);
                ta = fma2(q23.y, Ga[3], ta);
                ta = fma2(q4,    Ga[4], ta);
                u64 tb = mul2(q01.x, Gb[0]);
                tb = fma2(q01.y, Gb[1], tb);
                tb = fma2(q23.x, Gb[2], tb);
                tb = fma2(q23.y, Gb[3], tb);
                tb = fma2(q4,    Gb[4], tb);

                e2a[w] = fma2(gda, ta, e2a[w]);
                e2b[w] = fma2(gdb, tb, e2b[w]);
            }
        }

        float ea[4], eb[4];
#pragma unroll
        for (int w = 0; w < 4; w++) {
            float lo, hi;
            upk2(lo, hi, e2a[w]); ea[w] = lo + hi;
            upk2(lo, hi, e2b[w]); eb[w] = lo + hi;
        }
        feats[0][tid] = make_float4(ea[0], ea[1], ea[2], ea[3]);
        feats[1][tid] = make_float4(eb[0], eb[1], eb[2], eb[3]);
    }
    __syncthreads();

    // ---- packed warp-GEMM logits: 20 tasks (img,class) over 7 warps ----
#pragma unroll
    for (int r = 0; r < 3; r++) {
        const int task = warp + 7 * r;
        if (task < 20) {
            const int img = task / 10;
            const int c   = task % 10;
            const ulonglong2* fv = reinterpret_cast<const ulonglong2*>(&feats[img][0]);
            const ulonglong2* wv = reinterpret_cast<const ulonglong2*>(W + c * 784);
            u64 acc2 = 0ull;
#pragma unroll
            for (int k = 0; k < 7; k++) {
                const int p = 32 * k + lane;
                if (p < 196) {
                    const ulonglong2 f = fv[p];
                    const ulonglong2 wq = wv[p];
                    acc2 = fma2(f.x, wq.x, acc2);
                    acc2 = fma2(f.y, wq.y, acc2);
                }
            }
            float lo, hi;
            upk2(lo, hi, acc2);
            float acc = lo + hi;
#pragma unroll
            for (int off = 16; off > 0; off >>= 1)
                acc += __shfl_xor_sync(0xffffffffu, acc, off);
            if (lane == 0) slog[task] = acc + bias[c];
        }
    }
    __syncthreads();

    if (tid < 2) {
        const float* l = slog + 10 * tid;
        float mx = l[0];
#pragma unroll
        for (int c = 1; c < 10; c++) mx = fmaxf(mx, l[c]);
        float se = 0.0f;
#pragma unroll
        for (int c = 0; c < 10; c++) se += expf(l[c] - mx);
        slse[tid] = mx + logf(se);
    }
    __syncthreads();

    if (tid < 20) {
        const int img = tid / 10;
        if (img == 0 || has1)
            out[(size_t)(b0 + img) * 10 + (tid % 10)] = slog[tid] - slse[img];
    }
}

extern "C" void kernel_launch(void* const* d_in, const int* in_sizes, int n_in,
                              void* d_out, int out_size) {
    const float* x    = (const float*)d_in[0];   // (B,1,28,28)
    const float* vp   = (const float*)d_in[1];   // (3,8)
    const float* W    = (const float*)d_in[2];   // (10,784)
    const float* bias = (const float*)d_in[3];   // (10,)
    float* out = (float*)d_out;

    const int B = in_sizes[0] / 784;
    precompute_A_kernel<<<1, 324>>>(vp);
    quanv_fused6_kernel<<<(B + 1) / 2, 224>>>(x, W, bias, out, B);
}

// round 7
// speedup vs baseline: 1.0749x; 1.0749x over previous
#include <cuda_runtime.h>
#include <math.h>

// ---------------------------------------------------------------------------
// Gate templates (compile-time masks). Wire w <-> bit (3-w) of amp index.
// ---------------------------------------------------------------------------
template<int M>
__device__ __forceinline__ void ry_gate(float sr[16], float si[16], float c, float s) {
#pragma unroll
    for (int i = 0; i < 16; i++) {
        if (!(i & M)) {
            const int j = i | M;
            float a0r = sr[i], a0i = si[i], a1r = sr[j], a1i = si[j];
            sr[i] = c * a0r - s * a1r;
            si[i] = c * a0i - s * a1i;
            sr[j] = s * a0r + c * a1r;
            si[j] = s * a0i + c * a1i;
        }
    }
}

template<int M>
__device__ __forceinline__ void rz_gate(float sr[16], float si[16], float c, float s) {
#pragma unroll
    for (int i = 0; i < 16; i++) {
        float sg = (i & M) ? s : -s;
        float rr = sr[i], ii = si[i];
        sr[i] = c * rr - sg * ii;
        si[i] = c * ii + sg * rr;
    }
}

template<int CM, int TM>
__device__ __forceinline__ void cx_gate(float sr[16], float si[16]) {
#pragma unroll
    for (int i = 0; i < 16; i++) {
        if ((i & CM) && !(i & TM)) {
            const int j = i | TM;
            float t;
            t = sr[i]; sr[i] = sr[j]; sr[j] = t;
            t = si[i]; si[i] = si[j]; si[j] = t;
        }
    }
}

// Coefficient tensor, layout [i(a12)][w*9 + j(a34)]: 9 rows x 36 floats.
__device__ float g_A[9 * 36];

// ---------------------------------------------------------------------------
// Precompute kernel (1 block): U, O_w = U^dag Z_w U, multilinear coeffs.
// ---------------------------------------------------------------------------
__global__ void precompute_A_kernel(const float* __restrict__ vp) {
    __shared__ float vc[24], vs[24];
    __shared__ float Ur[16][16], Ui[16][16];
    __shared__ float ReO[4][16][16];

    const int tid = threadIdx.x;

    if (tid < 24) {
        float ss, cc;
        __sincosf(vp[tid] * 0.5f, &ss, &cc);
        vc[tid] = cc;
        vs[tid] = ss;
    }
    __syncthreads();

    if (tid < 16) {
        float sr[16], si[16];
#pragma unroll
        for (int i = 0; i < 16; i++) { sr[i] = 0.0f; si[i] = 0.0f; }
        sr[tid] = 1.0f;

#pragma unroll
        for (int l = 0; l < 3; l++) {
            const float* lc = vc + l * 8;
            const float* ls = vs + l * 8;
            ry_gate<8>(sr, si, lc[0], ls[0]); rz_gate<8>(sr, si, lc[1], ls[1]);
            ry_gate<4>(sr, si, lc[1], ls[1]); rz_gate<4>(sr, si, lc[2], ls[2]);
            ry_gate<2>(sr, si, lc[2], ls[2]); rz_gate<2>(sr, si, lc[3], ls[3]);
            ry_gate<1>(sr, si, lc[3], ls[3]); rz_gate<1>(sr, si, lc[4], ls[4]);
            cx_gate<8, 4>(sr, si);
            cx_gate<4, 2>(sr, si);
            cx_gate<2, 1>(sr, si);
            cx_gate<1, 8>(sr, si);
        }
#pragma unroll
        for (int k = 0; k < 16; k++) { Ur[k][tid] = sr[k]; Ui[k][tid] = si[k]; }
    }
    __syncthreads();

    if (tid < 256) {
        const int i = tid >> 4;
        const int j = tid & 15;
        float acc[4] = {0.0f, 0.0f, 0.0f, 0.0f};
#pragma unroll
        for (int k = 0; k < 16; k++) {
            float t = Ur[k][i] * Ur[k][j] + Ui[k][i] * Ui[k][j];
#pragma unroll
            for (int w = 0; w < 4; w++)
                acc[w] += (k & (8 >> w)) ? -t : t;
        }
#pragma unroll
        for (int w = 0; w < 4; w++) ReO[w][i][j] = acc[w];
    }
    __syncthreads();

    if (tid < 324) {
        const int w = tid / 81;
        const int a = tid % 81;
        const int a0 = a / 27, a1 = (a / 9) % 3, a2 = (a / 3) % 3, a3 = a % 3;
        const int zm = (a0 == 1 ? 8 : 0) | (a1 == 1 ? 4 : 0) | (a2 == 1 ? 2 : 0) | (a3 == 1 ? 1 : 0);
        const int xm = (a0 == 2 ? 8 : 0) | (a1 == 2 ? 4 : 0) | (a2 == 2 ? 2 : 0) | (a3 == 2 ? 1 : 0);
        float acc = 0.0f;
#pragma unroll
        for (int i = 0; i < 16; i++) {
            float v = ReO[w][i][i ^ xm];
            acc += (__popc(i & zm) & 1) ? -v : v;
        }
        const int a12 = a0 * 3 + a1;
        const int a34 = a2 * 3 + a3;
        g_A[a12 * 36 + w * 9 + a34] = acc * 0.0625f;
    }
}

// g12[i] from (c0,s0,c1,s1) at compile-time index i = iu*3+iv, u=(1,c0,s0), v=(1,c1,s1)
template<int I>
__device__ __forceinline__ float g12_of(float c0, float s0, float c1, float s1) {
    constexpr int IU = I / 3, IV = I % 3;
    const float u = (IU == 0) ? 1.0f : (IU == 1 ? c0 : s0);
    const float v = (IV == 0) ? 1.0f : (IV == 1 ? c1 : s1);
    if (IU == 0) return v;
    if (IV == 0) return u;
    return u * v;
}

// Factored inner product: t = sum_j aw[j] * (u2 (x) v3)[j], 8 FMA.
__device__ __forceinline__ float dot9f(const float* aw, float c2, float s2, float c3, float s3) {
    float m0 = fmaf(c3, aw[1], aw[0]); m0 = fmaf(s3, aw[2], m0);
    float m1 = fmaf(c3, aw[4], aw[3]); m1 = fmaf(s3, aw[5], m1);
    float m2 = fmaf(c3, aw[7], aw[6]); m2 = fmaf(s3, aw[8], m2);
    float t  = fmaf(c2, m1, m0);
    return fmaf(s2, m2, t);
}

// ---------------------------------------------------------------------------
// Main fused kernel: one block per IMAGE PAIR, factored contraction.
// ---------------------------------------------------------------------------
__global__ __launch_bounds__(224, 6) void quanv_fused7_kernel(
    const float* __restrict__ x,     // (B,1,28,28)
    const float* __restrict__ W,     // (10,784)
    const float* __restrict__ bias,  // (10,)
    float* __restrict__ out,         // (B,10)
    int B)
{
    const int b0   = 2 * blockIdx.x;
    const int b1   = b0 + 1;
    const bool has1 = (b1 < B);
    const int tid  = threadIdx.x;
    const int warp = tid >> 5;
    const int lane = tid & 31;

    __shared__ __align__(16) float sA[9 * 36];
    __shared__ __align__(16) float4 feats[2][196];
    __shared__ float slog[20];
    __shared__ float slse[2];

    for (int i = tid; i < 9 * 36; i += 224)
        sA[i] = g_A[i];
    __syncthreads();

    if (tid < 196) {
        const int r14 = tid / 14;
        const int c14 = tid % 14;
        const int off = (2 * r14) * 28 + 2 * c14;

        // ---- per-image angle scalars (4 per half-pair) ----
        float c0a, s0a, c1a, s1a, c2a, s2a, c3a, s3a;
        {
            const float* xa = x + (size_t)b0 * 784;
            const float2 t2 = *reinterpret_cast<const float2*>(xa + off);
            const float2 b2 = *reinterpret_cast<const float2*>(xa + off + 28);
            __sincosf(t2.x, &s0a, &c0a);
            __sincosf(t2.y, &s1a, &c1a);
            __sincosf(b2.x, &s2a, &c2a);
            __sincosf(b2.y, &s3a, &c3a);
        }
        float c0b, s0b, c1b, s1b, c2b, s2b, c3b, s3b;
        if (has1) {
            const float* xb = x + (size_t)b1 * 784;
            const float2 t2 = *reinterpret_cast<const float2*>(xb + off);
            const float2 b2 = *reinterpret_cast<const float2*>(xb + off + 28);
            __sincosf(t2.x, &s0b, &c0b);
            __sincosf(t2.y, &s1b, &c1b);
            __sincosf(b2.x, &s2b, &c2b);
            __sincosf(b2.y, &s3b, &c3b);
        } else {
            c0b = s0b = c1b = s1b = c2b = s2b = c3b = s3b = 0.0f;
        }

        float e0[4] = {0.f, 0.f, 0.f, 0.f};
        float e1[4] = {0.f, 0.f, 0.f, 0.f};

        // i-loop (compile-time unrolled so g12_of<I> folds)
#pragma unroll
        for (int i = 0; i < 9; i++) {
            float av[36];
#pragma unroll
            for (int q = 0; q < 9; q++)
                *reinterpret_cast<float4*>(av + 4 * q) =
                    *reinterpret_cast<const float4*>(&sA[i * 36 + 4 * q]);

            float ga, gb;
            switch (i) {
                case 0: ga = 1.0f;      gb = 1.0f;      break;
                case 1: ga = c1a;       gb = c1b;       break;
                case 2: ga = s1a;       gb = s1b;       break;
                case 3: ga = c0a;       gb = c0b;       break;
                case 4: ga = c0a * c1a; gb = c0b * c1b; break;
                case 5: ga = c0a * s1a; gb = c0b * s1b; break;
                case 6: ga = s0a;       gb = s0b;       break;
                case 7: ga = s0a * c1a; gb = s0b * c1b; break;
                default: ga = s0a * s1a; gb = s0b * s1b; break;
            }

#pragma unroll
            for (int w = 0; w < 4; w++) {
                const float* aw = av + 9 * w;
                const float ta = dot9f(aw, c2a, s2a, c3a, s3a);
                const float tb = dot9f(aw, c2b, s2b, c3b, s3b);
                e0[w] = fmaf(ga, ta, e0[w]);
                e1[w] = fmaf(gb, tb, e1[w]);
            }
        }

        feats[0][tid] = make_float4(e0[0], e0[1], e0[2], e0[3]);
        feats[1][tid] = make_float4(e1[0], e1[1], e1[2], e1[3]);
    }
    __syncthreads();

    // ---- warp-GEMM logits: 20 tasks (img,class) over 7 warps ----
#pragma unroll
    for (int r = 0; r < 3; r++) {
        const int task = warp + 7 * r;
        if (task < 20) {
            const int img = task / 10;
            const int c   = task % 10;
            const float* wrow = W + c * 784;
            float acc = 0.0f;
#pragma unroll
            for (int k = 0; k < 6; k++) {
                const int p = 32 * k + lane;
                const float4 fv = feats[img][p];
                const float4 wv = *reinterpret_cast<const float4*>(wrow + 4 * p);
                acc = fmaf(fv.x, wv.x, acc);
                acc = fmaf(fv.y, wv.y, acc);
                acc = fmaf(fv.z, wv.z, acc);
                acc = fmaf(fv.w, wv.w, acc);
            }
            if (lane < 4) {
                const int p = 192 + lane;
                const float4 fv = feats[img][p];
                const float4 wv = *reinterpret_cast<const float4*>(wrow + 4 * p);
                acc = fmaf(fv.x, wv.x, acc);
                acc = fmaf(fv.y, wv.y, acc);
                acc = fmaf(fv.z, wv.z, acc);
                acc = fmaf(fv.w, wv.w, acc);
            }
#pragma unroll
            for (int off = 16; off > 0; off >>= 1)
                acc += __shfl_xor_sync(0xffffffffu, acc, off);
            if (lane == 0) slog[task] = acc + bias[c];
        }
    }
    __syncthreads();

    if (tid < 2) {
        const float* l = slog + 10 * tid;
        float mx = l[0];
#pragma unroll
        for (int c = 1; c < 10; c++) mx = fmaxf(mx, l[c]);
        float se = 0.0f;
#pragma unroll
        for (int c = 0; c < 10; c++) se += expf(l[c] - mx);
        slse[tid] = mx + logf(se);
    }
    __syncthreads();

    if (tid < 20) {
        const int img = tid / 10;
        if (img == 0 || has1)
            out[(size_t)(b0 + img) * 10 + (tid % 10)] = slog[tid] - slse[img];
    }
}

extern "C" void kernel_launch(void* const* d_in, const int* in_sizes, int n_in,
                              void* d_out, int out_size) {
    const float* x    = (const float*)d_in[0];   // (B,1,28,28)
    const float* vp   = (const float*)d_in[1];   // (3,8)
    const float* W    = (const float*)d_in[2];   // (10,784)
    const float* bias = (const float*)d_in[3];   // (10,)
    float* out = (float*)d_out;

    const int B = in_sizes[0] / 784;
    precompute_A_kernel<<<1, 324>>>(vp);
    quanv_fused7_kernel<<<(B + 1) / 2, 224>>>(x, W, bias, out, B);
}